// round 2
// baseline (speedup 1.0000x reference)
#include <cuda_runtime.h>

// MPS contraction: per batch b, carry = M_{0}; for s=1..63: carry = carry @ M_s;
// out[b] = trace(carry). M_s = stack[s, :, bit(b,s), :], bit = x[b,s] > 0.
//
// One CTA per batch. 256 threads as 16x16, each thread owns an 8x8 tile of the
// 128x128 carry. Carry double-buffered in SMEM (row pad 130 floats: conflict-free
// column reads + 8B-aligned u64 stores). B matrix staged in SMEM each step.
// Inner product uses packed fma.rn.f32x2 (sm_103a FFMA2) for 2x fp32 FMA rate.

#define NSPIN 64
#define D     128
#define PAD   130   // floats per carry row (even -> u64-aligned, conflict-free cols)

__device__ __forceinline__ unsigned long long ffma2(unsigned long long a,
                                                    unsigned long long b,
                                                    unsigned long long c) {
    unsigned long long d;
    asm("fma.rn.f32x2 %0, %1, %2, %3;" : "=l"(d) : "l"(a), "l"(b), "l"(c));
    return d;
}

__device__ __forceinline__ unsigned long long pack2(float a) {
    unsigned long long r;
    asm("mov.b64 %0, {%1, %1};" : "=l"(r) : "f"(a));
    return r;
}

extern __shared__ float smem_raw[];

__global__ __launch_bounds__(256, 1)
void mps_kernel(const float* __restrict__ x,
                const float* __restrict__ stack,
                float* __restrict__ out)
{
    float* A0   = smem_raw;                       // 128*130 floats
    float* A1   = smem_raw + D * PAD;             // 128*130 floats
    float* Bs   = smem_raw + 2 * D * PAD;         // 128*128 floats
    int*   bits = (int*)(smem_raw + 2 * D * PAD + D * D);  // 64 ints
    float* red  = (float*)bits;                   // reused after main loop

    const int tid = threadIdx.x;
    const int tx  = tid & 15;
    const int ty  = tid >> 4;
    const int b   = blockIdx.x;

    // Spin bits for this batch
    if (tid < NSPIN) bits[tid] = (x[b * NSPIN + tid] > 0.0f) ? 1 : 0;

    // carry := M_0  (load into padded A0, float2 granularity)
    {
        const float xv   = x[b * NSPIN + 0];
        const float2* s2 = (const float2*)(stack + ((xv > 0.0f) ? D : 0));
        float2* dst      = (float2*)A0;
        #pragma unroll
        for (int t = 0; t < 32; ++t) {
            int m   = tid + t * 256;   // 0..8191 float2s
            int row = m >> 6;          // 64 float2 per logical row
            int c2  = m & 63;
            dst[row * (PAD / 2) + c2] = s2[row * 128 + c2]; // src row stride = 256 floats
        }
    }
    __syncthreads();

    float* Acur = A0;
    float* Anxt = A1;
    unsigned long long c[8][4];

    for (int s = 1; s < NSPIN; ++s) {
        const int bit = bits[s];

        // Stage B = stack[s, :, bit, :] into SMEM (rows of 128 floats, coalesced)
        {
            const float4* src = (const float4*)(stack + s * (D * 2 * D) + bit * D);
            float4* dst = (float4*)Bs;
            #pragma unroll
            for (int t = 0; t < 16; ++t) {
                int m   = tid + t * 256;  // 0..4095 float4s
                int row = m >> 5;         // 32 float4 per row
                int c4  = m & 31;
                dst[row * 32 + c4] = src[row * 64 + c4]; // src row stride = 256 floats
            }
        }
        __syncthreads();

        #pragma unroll
        for (int r = 0; r < 8; ++r)
            #pragma unroll
            for (int j = 0; j < 4; ++j)
                c[r][j] = 0ull;

        const float* arow = Acur + (ty * 8) * PAD;
        const ulonglong2* bbase = ((const ulonglong2*)Bs) + tx * 2;

        #pragma unroll 8
        for (int k = 0; k < D; ++k) {
            ulonglong2 b0 = bbase[k * 32];
            ulonglong2 b1 = bbase[k * 32 + 1];
            #pragma unroll
            for (int r = 0; r < 8; ++r) {
                unsigned long long aa = pack2(arow[r * PAD + k]);
                c[r][0] = ffma2(aa, b0.x, c[r][0]);
                c[r][1] = ffma2(aa, b0.y, c[r][1]);
                c[r][2] = ffma2(aa, b1.x, c[r][2]);
                c[r][3] = ffma2(aa, b1.y, c[r][3]);
            }
        }

        // Write C tile into the other carry buffer (u64 stores, aligned by PAD=130)
        unsigned long long* wbase = (unsigned long long*)Anxt + tx * 4;
        #pragma unroll
        for (int r = 0; r < 8; ++r) {
            int i = ty * 8 + r;
            #pragma unroll
            for (int j = 0; j < 4; ++j)
                wbase[i * (PAD / 2) + j] = c[r][j];
        }
        __syncthreads();

        float* t = Acur; Acur = Anxt; Anxt = t;
    }

    // out[b] = trace(carry)
    float v = 0.0f;
    if (tid < D) v = Acur[tid * PAD + tid];
    #pragma unroll
    for (int o = 16; o > 0; o >>= 1)
        v += __shfl_down_sync(0xffffffffu, v, o);
    __syncthreads();   // done with bits[]; reuse as reduction scratch
    if (tid < D && (tid & 31) == 0) red[tid >> 5] = v;
    __syncthreads();
    if (tid == 0) out[b] = red[0] + red[1] + red[2] + red[3];
}

extern "C" void kernel_launch(void* const* d_in, const int* in_sizes, int n_in,
                              void* d_out, int out_size)
{
    // Inputs per metadata order: x (1024*64 f32), stack (64*128*2*128 f32).
    // Defensive: identify by element count.
    const float* x;
    const float* stack;
    if (in_sizes[0] == 1024 * NSPIN) {
        x     = (const float*)d_in[0];
        stack = (const float*)d_in[1];
    } else {
        stack = (const float*)d_in[0];
        x     = (const float*)d_in[1];
    }
    float* out = (float*)d_out;

    const size_t smem_bytes = (size_t)(2 * D * PAD + D * D + 64) * sizeof(float); // 198,912 B
    cudaFuncSetAttribute(mps_kernel, cudaFuncAttributeMaxDynamicSharedMemorySize,
                         (int)smem_bytes);
    mps_kernel<<<1024, 256, smem_bytes>>>(x, stack, out);
}